// round 2
// baseline (speedup 1.0000x reference)
#include <cuda_runtime.h>
#include <math.h>

// ---------------------------------------------------------------------------
// Problem constants
// ---------------------------------------------------------------------------
#define VOCABN 32000
#define HSN    256
#define BATCH  128
#define BTN    256          // 2*BATCH : both trees batched together
#define NTREEN 1023
#define NIOU   768          // 3*HS

// ---------------------------------------------------------------------------
// Scratch (device globals; no dynamic allocation allowed)
// ---------------------------------------------------------------------------
__device__ float g_table [(size_t)VOCABN * NIOU];            //  98 MB: W_iou @ emb[v]
__device__ float g_h     [(size_t)BTN * NTREEN * HSN];       // 268 MB
__device__ float g_c     [(size_t)BTN * NTREEN * HSN];       // 268 MB
__device__ float g_fpre  [(size_t)131072 * 256];             // 134 MB (lvl8: 2*65536 rows)
__device__ float g_ioupre[(size_t)65536  * 768];             // 201 MB (lvl8: 65536 rows)

// ---------------------------------------------------------------------------
// Activations (rel err ~1e-6, fine vs 1e-3 budget)
// ---------------------------------------------------------------------------
__device__ __forceinline__ float sigf(float x)   { return 1.0f / (1.0f + __expf(-x)); }
__device__ __forceinline__ float tanhf_(float x) { return 2.0f / (1.0f + __expf(-2.0f * x)) - 1.0f; }

// ---------------------------------------------------------------------------
// Tiled fp32 GEMM, K = 256 fixed.  C[M,N] = A[M,256] @ W[N,256]^T
// MODE 0: A row r = emb[r]                  -> C = g_table, N = 768
// MODE 1: A row r = h[child(r)]             -> C = g_fpre,  N = 256
// MODE 2: A row r = h[ch0(r)] + h[ch1(r)]   -> C = g_ioupre,N = 768
// Row decode (MODE 1): r = 2*i + s, i = j*256 + bt, node = base + j
// Row decode (MODE 2): r = i       = j*256 + bt
// All M, N are multiples of 64 by construction -> no bounds checks.
// ---------------------------------------------------------------------------
#define TBM 64
#define TBN 64
#define TBK 16

template<int MODE>
__global__ __launch_bounds__(256) void gemm_k256(
    const float* __restrict__ A0,   // emb (MODE 0 only)
    const float* __restrict__ W,
    int base)                       // level base (MODE 1/2)
{
    __shared__ float As[TBK][TBM + 4];
    __shared__ float Bs[TBK][TBN + 4];

    const int N = (MODE == 1) ? 256 : 768;
    float* __restrict__ C = (MODE == 0) ? g_table : (MODE == 1) ? g_fpre : g_ioupre;

    const int bm  = blockIdx.x * TBM;
    const int bn  = blockIdx.y * TBN;
    const int tid = threadIdx.x;
    const int tx  = tid & 15;        // 0..15  -> 4 output cols
    const int ty  = tid >> 4;        // 0..15  -> 4 output rows
    const int lr  = tid >> 2;        // 0..63  tile row this thread loads
    const int lk  = (tid & 3) << 2;  // 0,4,8,12 k offset (float4)

    // A row pointers for the row this thread loads
    const float* ar0;
    const float* ar1 = nullptr;
    {
        const int r = bm + lr;
        if (MODE == 0) {
            ar0 = A0 + (size_t)r * 256;
        } else if (MODE == 1) {
            const int i = r >> 1, s = r & 1;
            const int j = i >> 8, bt = i & 255;
            const int node = base + j;
            ar0 = g_h + ((size_t)bt * NTREEN + (2 * node + 1 + s)) * 256;
        } else {
            const int j = r >> 8, bt = r & 255;
            const int node = base + j;
            ar0 = g_h + ((size_t)bt * NTREEN + (2 * node + 1)) * 256;
            ar1 = g_h + ((size_t)bt * NTREEN + (2 * node + 2)) * 256;
        }
    }
    const float* wr = W + (size_t)(bn + lr) * 256;

    float acc[4][4] = {};

    for (int k0 = 0; k0 < 256; k0 += TBK) {
        float4 a = *(const float4*)(ar0 + k0 + lk);
        if (MODE == 2) {
            float4 a1 = *(const float4*)(ar1 + k0 + lk);
            a.x += a1.x; a.y += a1.y; a.z += a1.z; a.w += a1.w;
        }
        float4 b = *(const float4*)(wr + k0 + lk);

        As[lk + 0][lr] = a.x; As[lk + 1][lr] = a.y;
        As[lk + 2][lr] = a.z; As[lk + 3][lr] = a.w;
        Bs[lk + 0][lr] = b.x; Bs[lk + 1][lr] = b.y;
        Bs[lk + 2][lr] = b.z; Bs[lk + 3][lr] = b.w;
        __syncthreads();

        #pragma unroll
        for (int k = 0; k < TBK; k++) {
            float4 av = *(const float4*)&As[k][ty * 4];
            float4 bv = *(const float4*)&Bs[k][tx * 4];
            float am[4]  = { av.x, av.y, av.z, av.w };
            float bm_[4] = { bv.x, bv.y, bv.z, bv.w };
            #pragma unroll
            for (int m = 0; m < 4; m++)
                #pragma unroll
                for (int n = 0; n < 4; n++)
                    acc[m][n] = fmaf(am[m], bm_[n], acc[m][n]);
        }
        __syncthreads();
    }

    #pragma unroll
    for (int m = 0; m < 4; m++) {
        const int row = bm + ty * 4 + m;
        float4 v = make_float4(acc[m][0], acc[m][1], acc[m][2], acc[m][3]);
        *(float4*)&C[(size_t)row * N + bn + tx * 4] = v;
    }
}

// ---------------------------------------------------------------------------
// Leaf elementwise: iou = table[types[bt,node]] + b_iou; c = sig(i)*tanh(u);
// h = sig(o)*tanh(c).  One float4 lane-group per thread, 4 instances / block.
// ---------------------------------------------------------------------------
__global__ __launch_bounds__(256) void leaf_ew(
    const int* __restrict__ types1, const int* __restrict__ types2,
    const float* __restrict__ b_iou)
{
    const int tid  = blockIdx.x * 256 + threadIdx.x;
    const int hs4  = tid & 63;
    const int inst = tid >> 6;             // 0 .. 131071
    const int bt   = inst >> 9;            // 0 .. 255
    const int j    = inst & 511;
    const int node = 511 + j;

    const int v = (bt < BATCH) ? types1[bt * NTREEN + node]
                               : types2[(bt - BATCH) * NTREEN + node];

    const float4* t  = (const float4*)(g_table + (size_t)v * NIOU);
    const float4* bb = (const float4*)b_iou;

    float4 i4 = t[hs4],       b0 = bb[hs4];
    float4 o4 = t[64 + hs4],  b1 = bb[64 + hs4];
    float4 u4 = t[128 + hs4], b2 = bb[128 + hs4];

    float4 cn, hn;
    #define DOLANE(c_)                                             \
    {   float cv = sigf(i4.c_ + b0.c_) * tanhf_(u4.c_ + b2.c_);   \
        cn.c_ = cv;                                                \
        hn.c_ = sigf(o4.c_ + b1.c_) * tanhf_(cv); }
    DOLANE(x) DOLANE(y) DOLANE(z) DOLANE(w)
    #undef DOLANE

    const size_t rowoff = ((size_t)bt * NTREEN + node) * 256;
    ((float4*)(g_h + rowoff))[hs4] = hn;
    ((float4*)(g_c + rowoff))[hs4] = cn;
}

// ---------------------------------------------------------------------------
// Internal-level elementwise: consumes g_fpre (f gates) + g_ioupre (iou),
// reads children c, writes node h,c.
// ---------------------------------------------------------------------------
__global__ __launch_bounds__(256) void level_ew(
    const float* __restrict__ b_iou, const float* __restrict__ U_f_b, int base)
{
    const int tid = blockIdx.x * 256 + threadIdx.x;
    const int hs4 = tid & 63;
    const int i   = tid >> 6;
    const int j   = i >> 8, bt = i & 255;
    const int node = base + j;

    const size_t rc0 = ((size_t)bt * NTREEN + 2 * node + 1) * 256;
    const size_t rc1 = rc0 + 256;   // sibling is adjacent

    const float4 f0 = ((const float4*)(g_fpre + (size_t)(2 * i)     * 256))[hs4];
    const float4 f1 = ((const float4*)(g_fpre + (size_t)(2 * i + 1) * 256))[hs4];
    const float4 fb = ((const float4*)U_f_b)[hs4];
    const float4 c0 = ((const float4*)(g_c + rc0))[hs4];
    const float4 c1 = ((const float4*)(g_c + rc1))[hs4];

    const float4* ip = (const float4*)(g_ioupre + (size_t)i * NIOU);
    const float4 iI = ip[hs4], iO = ip[64 + hs4], iU = ip[128 + hs4];
    const float4* bb = (const float4*)b_iou;
    const float4 b0 = bb[hs4], b1 = bb[64 + hs4], b2 = bb[128 + hs4];

    float4 cn, hn;
    #define DOLANE(c_)                                                          \
    {   float csum = sigf(f0.c_ + fb.c_) * c0.c_ + sigf(f1.c_ + fb.c_) * c1.c_; \
        float cv = sigf(iI.c_ + b0.c_) * tanhf_(iU.c_ + b2.c_) + csum;          \
        cn.c_ = cv;                                                             \
        hn.c_ = sigf(iO.c_ + b1.c_) * tanhf_(cv); }
    DOLANE(x) DOLANE(y) DOLANE(z) DOLANE(w)
    #undef DOLANE

    const size_t rowoff = ((size_t)bt * NTREEN + node) * 256;
    ((float4*)(g_h + rowoff))[hs4] = hn;
    ((float4*)(g_c + rowoff))[hs4] = cn;
}

// ---------------------------------------------------------------------------
// Final: rep = mean over nodes; out = |rep1-rep2| @ cls_w^T + cls_b
// ---------------------------------------------------------------------------
__global__ __launch_bounds__(256) void final_k(
    const float* __restrict__ cls_w, const float* __restrict__ cls_b,
    float* __restrict__ out)
{
    const int b  = blockIdx.x;
    const int hs = threadIdx.x;

    const float* h1 = g_h + (size_t)b           * NTREEN * 256;
    const float* h2 = g_h + (size_t)(b + BATCH) * NTREEN * 256;

    float s1 = 0.f, s2 = 0.f;
    #pragma unroll 4
    for (int n = 0; n < NTREEN; n++) {
        s1 += h1[(size_t)n * 256 + hs];
        s2 += h2[(size_t)n * 256 + hs];
    }
    const float d = fabsf(s1 - s2) * (1.0f / (float)NTREEN);

    float v0 = d * cls_w[hs];
    float v1 = d * cls_w[256 + hs];

    #pragma unroll
    for (int off = 16; off > 0; off >>= 1) {
        v0 += __shfl_down_sync(0xffffffffu, v0, off);
        v1 += __shfl_down_sync(0xffffffffu, v1, off);
    }
    __shared__ float sm0[8], sm1[8];
    const int w = threadIdx.x >> 5, lane = threadIdx.x & 31;
    if (lane == 0) { sm0[w] = v0; sm1[w] = v1; }
    __syncthreads();
    if (threadIdx.x == 0) {
        float t0 = 0.f, t1 = 0.f;
        #pragma unroll
        for (int k = 0; k < 8; k++) { t0 += sm0[k]; t1 += sm1[k]; }
        out[b * 2 + 0] = t0 + cls_b[0];
        out[b * 2 + 1] = t1 + cls_b[1];
    }
}

// ---------------------------------------------------------------------------
// Launch: table GEMM -> leaves -> 9 levels (fGEMM, iouGEMM, ew) -> final
// ---------------------------------------------------------------------------
extern "C" void kernel_launch(void* const* d_in, const int* in_sizes, int n_in,
                              void* d_out, int out_size)
{
    (void)in_sizes; (void)n_in; (void)out_size;
    const int*   types1 = (const int*)  d_in[0];
    const int*   types2 = (const int*)  d_in[1];
    const float* emb    = (const float*)d_in[2];
    const float* W_iou  = (const float*)d_in[3];
    const float* U_iou  = (const float*)d_in[4];
    const float* b_iou  = (const float*)d_in[5];
    const float* U_f_w  = (const float*)d_in[6];
    const float* U_f_b  = (const float*)d_in[7];
    const float* cls_w  = (const float*)d_in[8];
    const float* cls_b  = (const float*)d_in[9];
    float* out = (float*)d_out;

    // 1) vocab table: g_table[v] = W_iou @ emb[v]   (32000 x 256 -> 768)
    gemm_k256<0><<<dim3(VOCABN / TBM, NIOU / TBN), 256>>>(emb, W_iou, 0);

    // 2) leaves (level 9): 256 bt * 512 leaves
    leaf_ew<<<(BTN * 512 * 64) / 256, 256>>>(types1, types2, b_iou);

    // 3) internal levels 8 .. 0
    for (int lvl = 8; lvl >= 0; --lvl) {
        const int n_l  = 1 << lvl;
        const int base = n_l - 1;
        const int inst = BTN * n_l;                       // instances this level
        gemm_k256<1><<<dim3(2 * inst / TBM, 256 / TBN), 256>>>(nullptr, U_f_w, base);
        gemm_k256<2><<<dim3(inst / TBM, NIOU / TBN), 256>>>(nullptr, U_iou, base);
        level_ew<<<inst / 4, 256>>>(b_iou, U_f_b, base);
    }

    // 4) classifier
    final_k<<<BATCH, 256>>>(cls_w, cls_b, out);
}

// round 4
// speedup vs baseline: 1.4073x; 1.4073x over previous
#include <cuda_runtime.h>
#include <cuda_bf16.h>
#include <stdint.h>
#include <math.h>

// ---------------------------------------------------------------------------
// Problem constants
// ---------------------------------------------------------------------------
#define VOCABN 32000
#define HSN    256
#define BATCH  128
#define BTN    256          // 2*BATCH
#define NTREEN 1023
#define NIOU   768

// ---------------------------------------------------------------------------
// Scratch (device globals)
// h is stored packed: u32 = (bf16(hi) << 16) | bf16(lo),  h = hi + lo
// ---------------------------------------------------------------------------
__device__ unsigned g_h  [(size_t)BTN * NTREEN * HSN];       // 268 MB packed hi/lo
__device__ float g_c     [(size_t)BTN * NTREEN * HSN];       // 268 MB fp32
__device__ float g_table [(size_t)VOCABN * NIOU];            //  98 MB
__device__ float g_fpre  [(size_t)131072 * 256];             // 134 MB
__device__ float g_ioupre[(size_t)65536  * 768];             // 201 MB

// ---------------------------------------------------------------------------
// Helpers
// ---------------------------------------------------------------------------
__device__ __forceinline__ float sigf(float x)   { return 1.0f / (1.0f + __expf(-x)); }
__device__ __forceinline__ float tanhf_(float x) { return 2.0f / (1.0f + __expf(-2.0f * x)) - 1.0f; }

__device__ __forceinline__ unsigned packhl(float x) {
    __nv_bfloat16 h = __float2bfloat16(x);
    float hf = __bfloat162float(h);
    __nv_bfloat16 l = __float2bfloat16(x - hf);
    return ((unsigned)__bfloat16_as_ushort(h) << 16) | (unsigned)__bfloat16_as_ushort(l);
}
__device__ __forceinline__ float unpackhl(unsigned p) {
    return __uint_as_float(p & 0xFFFF0000u) + __uint_as_float(p << 16);
}
__device__ __forceinline__ void split16(float x, unsigned short& hb, unsigned short& lb) {
    __nv_bfloat16 h = __float2bfloat16(x);
    float hf = __bfloat162float(h);
    __nv_bfloat16 l = __float2bfloat16(x - hf);
    hb = __bfloat16_as_ushort(h);
    lb = __bfloat16_as_ushort(l);
}
__device__ __forceinline__ uint4 pack8(const unsigned short v[8]) {
    uint4 r;
    r.x = v[0] | ((unsigned)v[1] << 16);
    r.y = v[2] | ((unsigned)v[3] << 16);
    r.z = v[4] | ((unsigned)v[5] << 16);
    r.w = v[6] | ((unsigned)v[7] << 16);
    return r;
}

__device__ __forceinline__ uint32_t smem_u32(const void* p) {
    uint32_t a;
    asm("{ .reg .u64 t; cvta.to.shared.u64 t, %1; cvt.u32.u64 %0, t; }" : "=r"(a) : "l"(p));
    return a;
}

// ---------------------------------------------------------------------------
// Baseline-PTX tensor ops: ldmatrix + mma.sync (bf16, fp32 accum)
// ---------------------------------------------------------------------------
__device__ __forceinline__ void ldm_x4(uint32_t r[4], uint32_t addr) {
    asm volatile("ldmatrix.sync.aligned.m8n8.x4.shared.b16 {%0,%1,%2,%3}, [%4];"
        : "=r"(r[0]), "=r"(r[1]), "=r"(r[2]), "=r"(r[3]) : "r"(addr));
}
__device__ __forceinline__ void ldm_x2(uint32_t r[2], uint32_t addr) {
    asm volatile("ldmatrix.sync.aligned.m8n8.x2.shared.b16 {%0,%1}, [%2];"
        : "=r"(r[0]), "=r"(r[1]) : "r"(addr));
}
__device__ __forceinline__ void mma_bf16(float c[4], const uint32_t a[4], const uint32_t b[2]) {
    asm volatile("mma.sync.aligned.m16n8k16.row.col.f32.bf16.bf16.f32 "
        "{%0,%1,%2,%3}, {%4,%5,%6,%7}, {%8,%9}, {%0,%1,%2,%3};"
        : "+f"(c[0]), "+f"(c[1]), "+f"(c[2]), "+f"(c[3])
        : "r"(a[0]), "r"(a[1]), "r"(a[2]), "r"(a[3]), "r"(b[0]), "r"(b[1]));
}

// SW128-style swizzle for 128B rows
#define SWZ(o) ((o) ^ (((o) >> 3) & 0x70))

// ---------------------------------------------------------------------------
// bf16 hi/lo-split GEMM via mma.sync.  C[M,N] = A[M,256] @ W[N,256]^T (fp32)
// CTA tile 128x128; K in 4 chunks of 64 staged via smem.
// MODE 0: A row r = emb[r] (fp32)            -> C = g_table, Nc = 768
// MODE 1: A row r = h[child(r)] (packed)     -> C = g_fpre,  Nc = 256
// MODE 2: A row r = h[ch0]+h[ch1] (packed)   -> C = g_ioupre,Nc = 768
// ---------------------------------------------------------------------------
#define TM 128
#define TN 128
#define SM_AH 0
#define SM_AL 16384
#define SM_BH 32768
#define SM_BL 49152
#define SM_TOTAL 65536

template<int MODE>
__global__ __launch_bounds__(256, 2) void gemm_mma(
    const float* __restrict__ A0,
    const float* __restrict__ W,
    int base)
{
    extern __shared__ char smem[];
    const uint32_t sb = smem_u32(smem);
    const int tid = threadIdx.x, wid = tid >> 5, lane = tid & 31;
    const int Nc = (MODE == 1) ? 256 : 768;
    float* __restrict__ C = (MODE == 0) ? g_table : (MODE == 1) ? g_fpre : g_ioupre;
    const int bm = blockIdx.x * TM;
    const int bn = blockIdx.y * TN;

    // ---- gmem source pointers (thread loads row = tid>>1, half = tid&1) ----
    const int arow = tid >> 1, ahalf = tid & 1;
    const float*    af  = nullptr;
    const unsigned* ap0 = nullptr;
    const unsigned* ap1 = nullptr;
    {
        const int r = bm + arow;
        if (MODE == 0) {
            af = A0 + (size_t)r * 256 + ahalf * 32;
        } else if (MODE == 1) {
            const int i = r >> 1, s = r & 1;
            const int j = i >> 8, bt = i & 255;
            const int node = base + j;
            ap0 = g_h + ((size_t)bt * NTREEN + (2 * node + 1 + s)) * 256 + ahalf * 32;
        } else {
            const int j = r >> 8, bt = r & 255;
            const int node = base + j;
            ap0 = g_h + ((size_t)bt * NTREEN + (2 * node + 1)) * 256 + ahalf * 32;
            ap1 = ap0 + 256;
        }
    }
    const float* wr = W + (size_t)(bn + arow) * 256 + ahalf * 32;

    // ---- warp tiling: 2(M) x 4(N) warps, warp tile 64x32 ----
    const int wm = (wid & 1) * 64;
    const int wn = (wid >> 1) * 32;

    float acc[4][4][4] = {};

    for (int kc = 0; kc < 4; kc++) {
        const int k0 = kc * 64;
        if (kc) __syncthreads();      // previous chunk's compute done

        // ---- A tile: 128 rows x 64 k-cols (this thread: 32 elems) ----
        #pragma unroll
        for (int q = 0; q < 4; q++) {
            unsigned short hb[8], lb[8];
            if (MODE == 1) {
                uint4 p0 = *(const uint4*)(ap0 + k0 + q * 8);
                uint4 p1 = *(const uint4*)(ap0 + k0 + q * 8 + 4);
                unsigned pv[8] = { p0.x, p0.y, p0.z, p0.w, p1.x, p1.y, p1.z, p1.w };
                #pragma unroll
                for (int e = 0; e < 8; e++) {
                    hb[e] = (unsigned short)(pv[e] >> 16);
                    lb[e] = (unsigned short)(pv[e] & 0xFFFFu);
                }
            } else if (MODE == 2) {
                uint4 p0 = *(const uint4*)(ap0 + k0 + q * 8);
                uint4 p1 = *(const uint4*)(ap0 + k0 + q * 8 + 4);
                uint4 s0 = *(const uint4*)(ap1 + k0 + q * 8);
                uint4 s1 = *(const uint4*)(ap1 + k0 + q * 8 + 4);
                unsigned pv[8] = { p0.x, p0.y, p0.z, p0.w, p1.x, p1.y, p1.z, p1.w };
                unsigned sv[8] = { s0.x, s0.y, s0.z, s0.w, s1.x, s1.y, s1.z, s1.w };
                #pragma unroll
                for (int e = 0; e < 8; e++)
                    split16(unpackhl(pv[e]) + unpackhl(sv[e]), hb[e], lb[e]);
            } else {
                float4 v0 = *(const float4*)(af + k0 + q * 8);
                float4 v1 = *(const float4*)(af + k0 + q * 8 + 4);
                float vv[8] = { v0.x, v0.y, v0.z, v0.w, v1.x, v1.y, v1.z, v1.w };
                #pragma unroll
                for (int e = 0; e < 8; e++) split16(vv[e], hb[e], lb[e]);
            }
            const unsigned sw = SWZ((unsigned)(arow * 128 + (ahalf * 32 + q * 8) * 2));
            *(uint4*)(smem + SM_AH + sw) = pack8(hb);
            *(uint4*)(smem + SM_AL + sw) = pack8(lb);
        }

        // ---- B tile: 128 n-rows x 64 k-cols (this thread: 32 elems) ----
        #pragma unroll
        for (int q = 0; q < 4; q++) {
            float4 v0 = *(const float4*)(wr + k0 + q * 8);
            float4 v1 = *(const float4*)(wr + k0 + q * 8 + 4);
            float vv[8] = { v0.x, v0.y, v0.z, v0.w, v1.x, v1.y, v1.z, v1.w };
            unsigned short hb[8], lb[8];
            #pragma unroll
            for (int e = 0; e < 8; e++) split16(vv[e], hb[e], lb[e]);
            const unsigned sw = SWZ((unsigned)(arow * 128 + (ahalf * 32 + q * 8) * 2));
            *(uint4*)(smem + SM_BH + sw) = pack8(hb);
            *(uint4*)(smem + SM_BL + sw) = pack8(lb);
        }

        __syncthreads();

        // ---- compute: 4 k16-groups, 3 passes (hh, hl, lh) ----
        #pragma unroll
        for (int kg = 0; kg < 4; kg++) {
            uint32_t bh[4][2], bl[4][2];
            #pragma unroll
            for (int nf = 0; nf < 4; nf++) {
                const int nrow = wn + nf * 8 + (lane & 7);
                const unsigned x = (unsigned)((kg * 16 + ((lane >> 3) & 1) * 8) * 2);
                const unsigned sw = (unsigned)nrow * 128u + (x ^ (((unsigned)nrow & 7u) << 4));
                ldm_x2(bh[nf], sb + SM_BH + sw);
                ldm_x2(bl[nf], sb + SM_BL + sw);
            }
            #pragma unroll
            for (int mf = 0; mf < 4; mf++) {
                const int mrow = wm + mf * 16 + (lane & 15);
                const unsigned x = (unsigned)((kg * 16 + (lane >> 4) * 8) * 2);
                const unsigned sw = (unsigned)mrow * 128u + (x ^ (((unsigned)mrow & 7u) << 4));
                uint32_t a[4];
                ldm_x4(a, sb + SM_AH + sw);
                #pragma unroll
                for (int nf = 0; nf < 4; nf++) {
                    mma_bf16(acc[mf][nf], a, bh[nf]);
                    mma_bf16(acc[mf][nf], a, bl[nf]);
                }
                ldm_x4(a, sb + SM_AL + sw);
                #pragma unroll
                for (int nf = 0; nf < 4; nf++)
                    mma_bf16(acc[mf][nf], a, bh[nf]);
            }
        }
    }

    // ---- epilogue: direct fp32 stores (float2 pairs, 8B aligned) ----
    #pragma unroll
    for (int mf = 0; mf < 4; mf++) {
        const int row = bm + wm + mf * 16 + (lane >> 2);
        #pragma unroll
        for (int nf = 0; nf < 4; nf++) {
            const int col = bn + wn + nf * 8 + (lane & 3) * 2;
            *(float2*)&C[(size_t)row * Nc + col] =
                make_float2(acc[mf][nf][0], acc[mf][nf][1]);
            *(float2*)&C[(size_t)(row + 8) * Nc + col] =
                make_float2(acc[mf][nf][2], acc[mf][nf][3]);
        }
    }
}

// ---------------------------------------------------------------------------
// Leaf elementwise (writes packed h)
// ---------------------------------------------------------------------------
__global__ __launch_bounds__(256) void leaf_ew(
    const int* __restrict__ types1, const int* __restrict__ types2,
    const float* __restrict__ b_iou)
{
    const int tid  = blockIdx.x * 256 + threadIdx.x;
    const int hs4  = tid & 63;
    const int inst = tid >> 6;
    const int bt   = inst >> 9;
    const int j    = inst & 511;
    const int node = 511 + j;

    const int v = (bt < BATCH) ? types1[bt * NTREEN + node]
                               : types2[(bt - BATCH) * NTREEN + node];

    const float4* t  = (const float4*)(g_table + (size_t)v * NIOU);
    const float4* bb = (const float4*)b_iou;

    float4 i4 = t[hs4],       b0 = bb[hs4];
    float4 o4 = t[64 + hs4],  b1 = bb[64 + hs4];
    float4 u4 = t[128 + hs4], b2 = bb[128 + hs4];

    float4 cn; uint4 hp;
    #define DOLANE(c_, hp_)                                          \
    {   float cv = sigf(i4.c_ + b0.c_) * tanhf_(u4.c_ + b2.c_);      \
        cn.c_ = cv;                                                  \
        hp.hp_ = packhl(sigf(o4.c_ + b1.c_) * tanhf_(cv)); }
    DOLANE(x, x) DOLANE(y, y) DOLANE(z, z) DOLANE(w, w)
    #undef DOLANE

    const size_t rowoff = ((size_t)bt * NTREEN + node) * 256;
    ((uint4*)(g_h + rowoff))[hs4]  = hp;
    ((float4*)(g_c + rowoff))[hs4] = cn;
}

// ---------------------------------------------------------------------------
// Internal-level elementwise (writes packed h)
// ---------------------------------------------------------------------------
__global__ __launch_bounds__(256) void level_ew(
    const float* __restrict__ b_iou, const float* __restrict__ U_f_b, int base)
{
    const int tid = blockIdx.x * 256 + threadIdx.x;
    const int hs4 = tid & 63;
    const int i   = tid >> 6;
    const int j   = i >> 8, bt = i & 255;
    const int node = base + j;

    const size_t rc0 = ((size_t)bt * NTREEN + 2 * node + 1) * 256;
    const size_t rc1 = rc0 + 256;

    const float4 f0 = ((const float4*)(g_fpre + (size_t)(2 * i)     * 256))[hs4];
    const float4 f1 = ((const float4*)(g_fpre + (size_t)(2 * i + 1) * 256))[hs4];
    const float4 fb = ((const float4*)U_f_b)[hs4];
    const float4 c0 = ((const float4*)(g_c + rc0))[hs4];
    const float4 c1 = ((const float4*)(g_c + rc1))[hs4];

    const float4* ip = (const float4*)(g_ioupre + (size_t)i * NIOU);
    const float4 iI = ip[hs4], iO = ip[64 + hs4], iU = ip[128 + hs4];
    const float4* bb = (const float4*)b_iou;
    const float4 b0 = bb[hs4], b1 = bb[64 + hs4], b2 = bb[128 + hs4];

    float4 cn; uint4 hp;
    #define DOLANE(c_, hp_)                                                     \
    {   float csum = sigf(f0.c_ + fb.c_) * c0.c_ + sigf(f1.c_ + fb.c_) * c1.c_; \
        float cv = sigf(iI.c_ + b0.c_) * tanhf_(iU.c_ + b2.c_) + csum;          \
        cn.c_ = cv;                                                             \
        hp.hp_ = packhl(sigf(iO.c_ + b1.c_) * tanhf_(cv)); }
    DOLANE(x, x) DOLANE(y, y) DOLANE(z, z) DOLANE(w, w)
    #undef DOLANE

    const size_t rowoff = ((size_t)bt * NTREEN + node) * 256;
    ((uint4*)(g_h + rowoff))[hs4]  = hp;
    ((float4*)(g_c + rowoff))[hs4] = cn;
}

// ---------------------------------------------------------------------------
// Final classifier (unpacks h)
// ---------------------------------------------------------------------------
__global__ __launch_bounds__(256) void final_k(
    const float* __restrict__ cls_w, const float* __restrict__ cls_b,
    float* __restrict__ out)
{
    const int b  = blockIdx.x;
    const int hs = threadIdx.x;

    const unsigned* h1 = g_h + (size_t)b           * NTREEN * 256;
    const unsigned* h2 = g_h + (size_t)(b + BATCH) * NTREEN * 256;

    float s1 = 0.f, s2 = 0.f;
    #pragma unroll 4
    for (int n = 0; n < NTREEN; n++) {
        s1 += unpackhl(h1[(size_t)n * 256 + hs]);
        s2 += unpackhl(h2[(size_t)n * 256 + hs]);
    }
    const float d = fabsf(s1 - s2) * (1.0f / (float)NTREEN);

    float v0 = d * cls_w[hs];
    float v1 = d * cls_w[256 + hs];

    #pragma unroll
    for (int off = 16; off > 0; off >>= 1) {
        v0 += __shfl_down_sync(0xffffffffu, v0, off);
        v1 += __shfl_down_sync(0xffffffffu, v1, off);
    }
    __shared__ float sm0[8], sm1[8];
    const int w = threadIdx.x >> 5, lane = threadIdx.x & 31;
    if (lane == 0) { sm0[w] = v0; sm1[w] = v1; }
    __syncthreads();
    if (threadIdx.x == 0) {
        float t0 = 0.f, t1 = 0.f;
        #pragma unroll
        for (int k = 0; k < 8; k++) { t0 += sm0[k]; t1 += sm1[k]; }
        out[b * 2 + 0] = t0 + cls_b[0];
        out[b * 2 + 1] = t1 + cls_b[1];
    }
}

// ---------------------------------------------------------------------------
// Launch
// ---------------------------------------------------------------------------
extern "C" void kernel_launch(void* const* d_in, const int* in_sizes, int n_in,
                              void* d_out, int out_size)
{
    (void)in_sizes; (void)n_in; (void)out_size;
    const int*   types1 = (const int*)  d_in[0];
    const int*   types2 = (const int*)  d_in[1];
    const float* emb    = (const float*)d_in[2];
    const float* W_iou  = (const float*)d_in[3];
    const float* U_iou  = (const float*)d_in[4];
    const float* b_iou  = (const float*)d_in[5];
    const float* U_f_w  = (const float*)d_in[6];
    const float* U_f_b  = (const float*)d_in[7];
    const float* cls_w  = (const float*)d_in[8];
    const float* cls_b  = (const float*)d_in[9];
    float* out = (float*)d_out;

    cudaFuncSetAttribute(gemm_mma<0>, cudaFuncAttributeMaxDynamicSharedMemorySize, SM_TOTAL);
    cudaFuncSetAttribute(gemm_mma<1>, cudaFuncAttributeMaxDynamicSharedMemorySize, SM_TOTAL);
    cudaFuncSetAttribute(gemm_mma<2>, cudaFuncAttributeMaxDynamicSharedMemorySize, SM_TOTAL);

    // 1) vocab table: g_table[v] = W_iou @ emb[v]
    gemm_mma<0><<<dim3(VOCABN / TM, NIOU / TN), 256, SM_TOTAL>>>(emb, W_iou, 0);

    // 2) leaves
    leaf_ew<<<(BTN * 512 * 64) / 256, 256>>>(types1, types2, b_iou);

    // 3) internal levels 8..0
    for (int lvl = 8; lvl >= 0; --lvl) {
        const int n_l  = 1 << lvl;
        const int base = n_l - 1;
        const int inst = BTN * n_l;
        gemm_mma<1><<<dim3(2 * inst / TM, 256 / TN), 256, SM_TOTAL>>>(nullptr, U_f_w, base);
        gemm_mma<2><<<dim3(inst / TM, NIOU / TN), 256, SM_TOTAL>>>(nullptr, U_iou, base);
        level_ew<<<inst / 4, 256>>>(b_iou, U_f_b, base);
    }

    // 4) classifier
    final_k<<<BATCH, 256>>>(cls_w, cls_b, out);
}

// round 7
// speedup vs baseline: 2.1411x; 1.5214x over previous
#include <cuda_runtime.h>
#include <cuda_bf16.h>
#include <stdint.h>
#include <math.h>

// ---------------------------------------------------------------------------
// Problem constants
// ---------------------------------------------------------------------------
#define VOCABN 32000
#define BATCH  128
#define BTN    256          // 2*BATCH
#define NTREEN 1023
#define NPRE   1280         // iou(768) | f0(256) | f1(256)

// ---------------------------------------------------------------------------
// Scratch (device globals) — h kept as separate bf16 hi/lo planes
// ---------------------------------------------------------------------------
__device__ __align__(16) __nv_bfloat16 g_emb_hi[(size_t)VOCABN * 256];
__device__ __align__(16) __nv_bfloat16 g_emb_lo[(size_t)VOCABN * 256];
__device__ __align__(16) __nv_bfloat16 g_Wt_hi[768 * 256];
__device__ __align__(16) __nv_bfloat16 g_Wt_lo[768 * 256];
__device__ __align__(16) __nv_bfloat16 g_Wc_hi[NPRE * 256];
__device__ __align__(16) __nv_bfloat16 g_Wc_lo[NPRE * 256];
__device__ __align__(16) __nv_bfloat16 g_h_hi[(size_t)BTN * NTREEN * 256];
__device__ __align__(16) __nv_bfloat16 g_h_lo[(size_t)BTN * NTREEN * 256];
__device__ __align__(16) __nv_bfloat16 g_hsum_hi[(size_t)65536 * 256];
__device__ __align__(16) __nv_bfloat16 g_hsum_lo[(size_t)65536 * 256];
__device__ __align__(16) float g_c    [(size_t)BTN * NTREEN * 256];
__device__ __align__(16) float g_pre  [(size_t)65536 * NPRE];
__device__ __align__(16) float g_table[(size_t)VOCABN * 768];

// ---------------------------------------------------------------------------
// Helpers
// ---------------------------------------------------------------------------
__device__ __forceinline__ float sigf(float x)   { return 1.0f / (1.0f + __expf(-x)); }
__device__ __forceinline__ float tanhf_(float x) { return 2.0f / (1.0f + __expf(-2.0f * x)) - 1.0f; }

__device__ __forceinline__ void split16(float x, unsigned short& hb, unsigned short& lb) {
    __nv_bfloat16 h = __float2bfloat16(x);
    float hf = __bfloat162float(h);
    __nv_bfloat16 l = __float2bfloat16(x - hf);
    hb = __bfloat16_as_ushort(h);
    lb = __bfloat16_as_ushort(l);
}
__device__ __forceinline__ float lo16f(unsigned u) { return __uint_as_float(u << 16); }
__device__ __forceinline__ float hi16f(unsigned u) { return __uint_as_float(u & 0xFFFF0000u); }

__device__ __forceinline__ uint32_t smem_u32(const void* p) {
    uint32_t a;
    asm("{ .reg .u64 t; cvta.to.shared.u64 t, %1; cvt.u32.u64 %0, t; }" : "=r"(a) : "l"(p));
    return a;
}

// ---------------------------------------------------------------------------
// Baseline-PTX tensor ops + cp.async
// ---------------------------------------------------------------------------
__device__ __forceinline__ void ldm_x4(uint32_t r[4], uint32_t addr) {
    asm volatile("ldmatrix.sync.aligned.m8n8.x4.shared.b16 {%0,%1,%2,%3}, [%4];"
        : "=r"(r[0]), "=r"(r[1]), "=r"(r[2]), "=r"(r[3]) : "r"(addr));
}
__device__ __forceinline__ void ldm_x2(uint32_t r[2], uint32_t addr) {
    asm volatile("ldmatrix.sync.aligned.m8n8.x2.shared.b16 {%0,%1}, [%2];"
        : "=r"(r[0]), "=r"(r[1]) : "r"(addr));
}
__device__ __forceinline__ void mma_bf16(float c[4], const uint32_t a[4], const uint32_t b[2]) {
    asm volatile("mma.sync.aligned.m16n8k16.row.col.f32.bf16.bf16.f32 "
        "{%0,%1,%2,%3}, {%4,%5,%6,%7}, {%8,%9}, {%0,%1,%2,%3};"
        : "+f"(c[0]), "+f"(c[1]), "+f"(c[2]), "+f"(c[3])
        : "r"(a[0]), "r"(a[1]), "r"(a[2]), "r"(a[3]), "r"(b[0]), "r"(b[1]));
}
#define CP16(dst, src) asm volatile("cp.async.cg.shared.global [%0], [%1], 16;" :: "r"(dst), "l"(src))
#define CP_COMMIT()    asm volatile("cp.async.commit_group;" ::: "memory")
#define CP_WAIT0()     asm volatile("cp.async.wait_group 0;" ::: "memory")

// ---------------------------------------------------------------------------
// Prep kernels — all device globals referenced FROM DEVICE CODE (the Round
// 5/6 bug was passing __device__ symbols as host-side kernel arguments).
// ---------------------------------------------------------------------------
__global__ __launch_bounds__(256) void split_emb(const float* __restrict__ src)
{
    const int idx = blockIdx.x * 256 + threadIdx.x;   // 0 .. VOCABN*256-1
    unsigned short h, l;
    split16(src[idx], h, l);
    g_emb_hi[idx] = __ushort_as_bfloat16(h);
    g_emb_lo[idx] = __ushort_as_bfloat16(l);
}

__global__ __launch_bounds__(256) void split_wt(const float* __restrict__ src)
{
    const int idx = blockIdx.x * 256 + threadIdx.x;   // 0 .. 768*256-1
    unsigned short h, l;
    split16(src[idx], h, l);
    g_Wt_hi[idx] = __ushort_as_bfloat16(h);
    g_Wt_lo[idx] = __ushort_as_bfloat16(l);
}

// Wc rows: [0:768)=U_iou, [768:1024)=U_f_w, [1024:1280)=U_f_w
__global__ __launch_bounds__(256) void build_wc(
    const float* __restrict__ U_iou, const float* __restrict__ U_f_w)
{
    const int idx = blockIdx.x * 256 + threadIdx.x;   // 0 .. 1280*256-1
    const int n = idx >> 8, k = idx & 255;
    const float v = (n < 768) ? U_iou[n * 256 + k]
                              : U_f_w[((n - 768) & 255) * 256 + k];
    unsigned short h, l;
    split16(v, h, l);
    g_Wc_hi[idx] = __ushort_as_bfloat16(h);
    g_Wc_lo[idx] = __ushort_as_bfloat16(l);
}

// hsum[i] = h[child0(i)] + h[child1(i)], re-split into hi/lo planes
__global__ __launch_bounds__(256) void hsum_k(int base)
{
    const int t   = blockIdx.x * 256 + threadIdx.x;
    const int hs4 = t & 63, i = t >> 6;
    const int j = i >> 8, bt = i & 255, node = base + j;
    const size_t rc = ((size_t)bt * NTREEN + 2 * node + 1) * 256;

    const uint2 h0 = ((const uint2*)(g_h_hi + rc))[hs4];
    const uint2 l0 = ((const uint2*)(g_h_lo + rc))[hs4];
    const uint2 h1 = ((const uint2*)(g_h_hi + rc + 256))[hs4];
    const uint2 l1 = ((const uint2*)(g_h_lo + rc + 256))[hs4];

    float s[4];
    s[0] = lo16f(h0.x) + lo16f(l0.x) + lo16f(h1.x) + lo16f(l1.x);
    s[1] = hi16f(h0.x) + hi16f(l0.x) + hi16f(h1.x) + hi16f(l1.x);
    s[2] = lo16f(h0.y) + lo16f(l0.y) + lo16f(h1.y) + lo16f(l1.y);
    s[3] = hi16f(h0.y) + hi16f(l0.y) + hi16f(h1.y) + hi16f(l1.y);

    unsigned short hb[4], lb[4];
    #pragma unroll
    for (int e = 0; e < 4; e++) split16(s[e], hb[e], lb[e]);

    const size_t o = (size_t)i * 256;
    ((uint2*)(g_hsum_hi + o))[hs4] =
        make_uint2(hb[0] | ((unsigned)hb[1] << 16), hb[2] | ((unsigned)hb[3] << 16));
    ((uint2*)(g_hsum_lo + o))[hs4] =
        make_uint2(lb[0] | ((unsigned)lb[1] << 16), lb[2] | ((unsigned)lb[3] << 16));
}

// ---------------------------------------------------------------------------
// bf16 hi/lo GEMM via mma.sync + cp.async.  C[M,N] = A[M,256] @ B[N,256]^T
// CTA tile 128x128; K = 4 chunks of 64; single 64KB stage, 2 CTAs/SM overlap.
// MODE 0: A = emb planes, B = Wt,  C = g_table (Nc=768, 6 n-tiles of 128)
// MODE 1: tiles 0-5: A = hsum (iou cols) | tiles 6,7: A = child0 (f0)
//         tiles 8,9: A = child1 (f1).    B = Wc,  C = g_pre (Nc=1280)
// smem: A_HI 16K | A_LO 16K | B_HI 16K | B_LO 16K
// ---------------------------------------------------------------------------
#define SM_AH 0u
#define SM_AL 16384u
#define SM_BH 32768u
#define SM_BL 49152u
#define SMT   65536

template<int MODE>
__global__ __launch_bounds__(256, 2) void gemm_f(int base)
{
    extern __shared__ char smem[];
    const uint32_t sb = smem_u32(smem);
    const int tid = threadIdx.x, wid = tid >> 5, lane = tid & 31;
    const int bm = blockIdx.x * 128;
    const int tile = blockIdx.y;
    const int bn = tile * 128;
    const int Nc = (MODE == 0) ? 768 : NPRE;

    // A source row pointer (row = tid>>1, half = tid&1 -> 32 elems)
    const __nv_bfloat16 *ahi, *alo;
    {
        const int r = bm + (tid >> 1);
        if (MODE == 0) {
            ahi = g_emb_hi + (size_t)r * 256;
            alo = g_emb_lo + (size_t)r * 256;
        } else if (tile < 6) {
            ahi = g_hsum_hi + (size_t)r * 256;
            alo = g_hsum_lo + (size_t)r * 256;
        } else {
            const int s = (tile - 6) >> 1;
            const int j = r >> 8, bt = r & 255, node = base + j;
            const size_t off = ((size_t)bt * NTREEN + 2 * node + 1 + s) * 256;
            ahi = g_h_hi + off;
            alo = g_h_lo + off;
        }
        ahi += (tid & 1) * 32;
        alo += (tid & 1) * 32;
    }
    // B source row pointer (row = tid>>1, half = tid&1)
    const __nv_bfloat16* bhi = ((MODE == 0) ? g_Wt_hi : g_Wc_hi)
                               + (size_t)(bn + (tid >> 1)) * 256 + (tid & 1) * 32;
    const __nv_bfloat16* blo = ((MODE == 0) ? g_Wt_lo : g_Wc_lo)
                               + (size_t)(bn + (tid >> 1)) * 256 + (tid & 1) * 32;

    const uint32_t rowoff = (uint32_t)(tid >> 1) * 128u;
    const uint32_t rxor   = (uint32_t)(((tid >> 1) & 7) << 4);

    const int wm = (wid & 1) * 64;
    const int wn = (wid >> 1) * 32;
    float acc[4][4][4] = {};

    #pragma unroll 1
    for (int kc = 0; kc < 4; kc++) {
        const int k0 = kc * 64;

        // ---- async loads: 16 x 16B per thread ----
        #pragma unroll
        for (int j = 0; j < 4; j++) {
            const uint32_t xo = (uint32_t)((tid & 1) * 64 + j * 16) ^ rxor;
            const uint32_t d = rowoff + xo;
            CP16(sb + SM_AH + d, ahi + k0 + j * 8);
            CP16(sb + SM_AL + d, alo + k0 + j * 8);
            CP16(sb + SM_BH + d, bhi + k0 + j * 8);
            CP16(sb + SM_BL + d, blo + k0 + j * 8);
        }
        CP_COMMIT();
        CP_WAIT0();
        __syncthreads();

        // ---- compute: 4 k16-groups, 3 passes (hh, hl, lh) ----
        #pragma unroll
        for (int kg = 0; kg < 4; kg++) {
            uint32_t bh[4][2], bl[4][2];
            #pragma unroll
            for (int nf = 0; nf < 4; nf++) {
                const uint32_t nrow = (uint32_t)(wn + nf * 8 + (lane & 7));
                const uint32_t x = (uint32_t)(kg * 32 + ((lane >> 3) & 1) * 16);
                const uint32_t sw = nrow * 128u + (x ^ ((nrow & 7u) << 4));
                ldm_x2(bh[nf], sb + SM_BH + sw);
                ldm_x2(bl[nf], sb + SM_BL + sw);
            }
            #pragma unroll
            for (int mf = 0; mf < 4; mf++) {
                const uint32_t mrow = (uint32_t)(wm + mf * 16 + (lane & 15));
                const uint32_t x = (uint32_t)(kg * 32 + (lane >> 4) * 16);
                const uint32_t sw = mrow * 128u + (x ^ ((mrow & 7u) << 4));
                uint32_t a[4];
                ldm_x4(a, sb + SM_AH + sw);       // A hi
                #pragma unroll
                for (int nf = 0; nf < 4; nf++) {
                    mma_bf16(acc[mf][nf], a, bh[nf]);   // hh
                    mma_bf16(acc[mf][nf], a, bl[nf]);   // hl
                }
                ldm_x4(a, sb + SM_AL + sw);       // A lo
                #pragma unroll
                for (int nf = 0; nf < 4; nf++)
                    mma_bf16(acc[mf][nf], a, bh[nf]);   // lh
            }
        }
        __syncthreads();
    }

    // ---- epilogue ----
    float* __restrict__ C = (MODE == 0) ? g_table : g_pre;
    #pragma unroll
    for (int mf = 0; mf < 4; mf++) {
        const int row = bm + wm + mf * 16 + (lane >> 2);
        #pragma unroll
        for (int nf = 0; nf < 4; nf++) {
            const int col = bn + wn + nf * 8 + (lane & 3) * 2;
            *(float2*)&C[(size_t)row * Nc + col] =
                make_float2(acc[mf][nf][0], acc[mf][nf][1]);
            *(float2*)&C[(size_t)(row + 8) * Nc + col] =
                make_float2(acc[mf][nf][2], acc[mf][nf][3]);
        }
    }
}

// ---------------------------------------------------------------------------
// h store helper: split 4 fp32 -> hi/lo planes
// ---------------------------------------------------------------------------
__device__ __forceinline__ void store_h4(size_t rowoff, int hs4, const float h[4]) {
    unsigned short hb[4], lb[4];
    #pragma unroll
    for (int e = 0; e < 4; e++) split16(h[e], hb[e], lb[e]);
    ((uint2*)(g_h_hi + rowoff))[hs4] =
        make_uint2(hb[0] | ((unsigned)hb[1] << 16), hb[2] | ((unsigned)hb[3] << 16));
    ((uint2*)(g_h_lo + rowoff))[hs4] =
        make_uint2(lb[0] | ((unsigned)lb[1] << 16), lb[2] | ((unsigned)lb[3] << 16));
}

// ---------------------------------------------------------------------------
// Leaf elementwise
// ---------------------------------------------------------------------------
__global__ __launch_bounds__(256) void leaf_ew(
    const int* __restrict__ types1, const int* __restrict__ types2,
    const float* __restrict__ b_iou)
{
    const int tid  = blockIdx.x * 256 + threadIdx.x;
    const int hs4  = tid & 63;
    const int inst = tid >> 6;
    const int bt   = inst >> 9;
    const int j    = inst & 511;
    const int node = 511 + j;

    const int v = (bt < BATCH) ? types1[bt * NTREEN + node]
                               : types2[(bt - BATCH) * NTREEN + node];

    const float4* t  = (const float4*)(g_table + (size_t)v * 768);
    const float4* bb = (const float4*)b_iou;

    float4 i4 = t[hs4],       b0 = bb[hs4];
    float4 o4 = t[64 + hs4],  b1 = bb[64 + hs4];
    float4 u4 = t[128 + hs4], b2 = bb[128 + hs4];

    float4 cn; float hv[4];
    #define DOLANE(c_, e_)                                           \
    {   float cv = sigf(i4.c_ + b0.c_) * tanhf_(u4.c_ + b2.c_);      \
        cn.c_ = cv;                                                  \
        hv[e_] = sigf(o4.c_ + b1.c_) * tanhf_(cv); }
    DOLANE(x, 0) DOLANE(y, 1) DOLANE(z, 2) DOLANE(w, 3)
    #undef DOLANE

    const size_t rowoff = ((size_t)bt * NTREEN + node) * 256;
    ((float4*)(g_c + rowoff))[hs4] = cn;
    store_h4(rowoff, hs4, hv);
}

// ---------------------------------------------------------------------------
// Internal-level elementwise: pre row = [iou(768) | f0(256) | f1(256)]
// ---------------------------------------------------------------------------
__global__ __launch_bounds__(256) void level_ew(
    const float* __restrict__ b_iou, const float* __restrict__ U_f_b, int base)
{
    const int tid = blockIdx.x * 256 + threadIdx.x;
    const int hs4 = tid & 63;
    const int i   = tid >> 6;
    const int j   = i >> 8, bt = i & 255;
    const int node = base + j;

    const size_t rc0 = ((size_t)bt * NTREEN + 2 * node + 1) * 256;
    const float4 c0 = ((const float4*)(g_c + rc0))[hs4];
    const float4 c1 = ((const float4*)(g_c + rc0 + 256))[hs4];

    const float4* pre = (const float4*)(g_pre + (size_t)i * NPRE);
    const float4 iI = pre[hs4], iO = pre[64 + hs4], iU = pre[128 + hs4];
    const float4 f0 = pre[192 + hs4], f1 = pre[256 + hs4];

    const float4* bb = (const float4*)b_iou;
    const float4 b0 = bb[hs4], b1 = bb[64 + hs4], b2 = bb[128 + hs4];
    const float4 fb = ((const float4*)U_f_b)[hs4];

    float4 cn; float hv[4];
    #define DOLANE(c_, e_)                                                      \
    {   float csum = sigf(f0.c_ + fb.c_) * c0.c_ + sigf(f1.c_ + fb.c_) * c1.c_; \
        float cv = sigf(iI.c_ + b0.c_) * tanhf_(iU.c_ + b2.c_) + csum;          \
        cn.c_ = cv;                                                             \
        hv[e_] = sigf(iO.c_ + b1.c_) * tanhf_(cv); }
    DOLANE(x, 0) DOLANE(y, 1) DOLANE(z, 2) DOLANE(w, 3)
    #undef DOLANE

    const size_t rowoff = ((size_t)bt * NTREEN + node) * 256;
    ((float4*)(g_c + rowoff))[hs4] = cn;
    store_h4(rowoff, hs4, hv);
}

// ---------------------------------------------------------------------------
// Final classifier
// ---------------------------------------------------------------------------
__global__ __launch_bounds__(256) void final_k(
    const float* __restrict__ cls_w, const float* __restrict__ cls_b,
    float* __restrict__ out)
{
    const int b  = blockIdx.x;
    const int hs = threadIdx.x;

    const size_t o1 = (size_t)b           * NTREEN * 256 + hs;
    const size_t o2 = (size_t)(b + BATCH) * NTREEN * 256 + hs;

    float s1 = 0.f, s2 = 0.f;
    #pragma unroll 4
    for (int n = 0; n < NTREEN; n++) {
        s1 += __bfloat162float(g_h_hi[o1 + (size_t)n * 256])
            + __bfloat162float(g_h_lo[o1 + (size_t)n * 256]);
        s2 += __bfloat162float(g_h_hi[o2 + (size_t)n * 256])
            + __bfloat162float(g_h_lo[o2 + (size_t)n * 256]);
    }
    const float d = fabsf(s1 - s2) * (1.0f / (float)NTREEN);

    float v0 = d * cls_w[hs];
    float v1 = d * cls_w[256 + hs];

    #pragma unroll
    for (int off = 16; off > 0; off >>= 1) {
        v0 += __shfl_down_sync(0xffffffffu, v0, off);
        v1 += __shfl_down_sync(0xffffffffu, v1, off);
    }
    __shared__ float sm0[8], sm1[8];
    const int w = threadIdx.x >> 5, lane = threadIdx.x & 31;
    if (lane == 0) { sm0[w] = v0; sm1[w] = v1; }
    __syncthreads();
    if (threadIdx.x == 0) {
        float t0 = 0.f, t1 = 0.f;
        #pragma unroll
        for (int k = 0; k < 8; k++) { t0 += sm0[k]; t1 += sm1[k]; }
        out[b * 2 + 0] = t0 + cls_b[0];
        out[b * 2 + 1] = t1 + cls_b[1];
    }
}

// ---------------------------------------------------------------------------
// Launch
// ---------------------------------------------------------------------------
extern "C" void kernel_launch(void* const* d_in, const int* in_sizes, int n_in,
                              void* d_out, int out_size)
{
    (void)in_sizes; (void)n_in; (void)out_size;
    const int*   types1 = (const int*)  d_in[0];
    const int*   types2 = (const int*)  d_in[1];
    const float* emb    = (const float*)d_in[2];
    const float* W_iou  = (const float*)d_in[3];
    const float* U_iou  = (const float*)d_in[4];
    const float* b_iou  = (const float*)d_in[5];
    const float* U_f_w  = (const float*)d_in[6];
    const float* U_f_b  = (const float*)d_in[7];
    const float* cls_w  = (const float*)d_in[8];
    const float* cls_b  = (const float*)d_in[9];
    float* out = (float*)d_out;

    cudaFuncSetAttribute(gemm_f<0>, cudaFuncAttributeMaxDynamicSharedMemorySize, SMT);
    cudaFuncSetAttribute(gemm_f<1>, cudaFuncAttributeMaxDynamicSharedMemorySize, SMT);

    // 0) prep: split emb + weights into bf16 hi/lo planes (device-side symbols)
    split_emb<<<VOCABN, 256>>>(emb);
    split_wt<<<768, 256>>>(W_iou);
    build_wc<<<NPRE, 256>>>(U_iou, U_f_w);

    // 1) vocab table: g_table[v] = W_iou @ emb[v]
    gemm_f<0><<<dim3(VOCABN / 128, 6), 256, SMT>>>(0);

    // 2) leaves
    leaf_ew<<<(BTN * 512 * 64) / 256, 256>>>(types1, types2, b_iou);

    // 3) internal levels 8..0  (hsum -> fused GEMM -> ew)
    for (int lvl = 8; lvl >= 0; --lvl) {
        const int base = (1 << lvl) - 1;
        const int inst = BTN << lvl;
        hsum_k<<<inst / 4, 256>>>(base);
        gemm_f<1><<<dim3(inst / 128, 10), 256, SMT>>>(base);
        level_ew<<<inst / 4, 256>>>(b_iou, U_f_b, base);
    }

    // 4) classifier
    final_k<<<BATCH, 256>>>(cls_w, cls_b, out);
}